// round 3
// baseline (speedup 1.0000x reference)
#include <cuda_runtime.h>
#include <cuda_bf16.h>

#define T_STEPS  2048
#define BATCH    4096
#define INSZ     8
#define HID      20
#define G4       80
#define KV       28      // INSZ + HID
#define GROUPS   14      // thread groups per CTA
#define NGE      28      // batch elems per CTA (2 per thread group)
#define NTHREADS 280     // GROUPS * HID
#define ROWF     64      // padded smem row (floats): duplicated pairs, 56 used
#define ROWB     256     // row bytes
#define BUFB     (NGE * ROWB)  // 7168 bytes per buffer

typedef unsigned long long u64;

__device__ __forceinline__ u64 fma2(u64 a, u64 b, u64 c) {
    u64 d;
    asm("fma.rn.f32x2 %0, %1, %2, %3;" : "=l"(d) : "l"(a), "l"(b), "l"(c));
    return d;
}
__device__ __forceinline__ u64 add2(u64 a, u64 b) {
    u64 d;
    asm("add.rn.f32x2 %0, %1, %2;" : "=l"(d) : "l"(a), "l"(b));
    return d;
}
__device__ __forceinline__ u64 pack2(float lo, float hi) {
    u64 d;
    asm("mov.b64 %0, {%1, %2};" : "=l"(d) : "f"(lo), "f"(hi));
    return d;
}
__device__ __forceinline__ void unpack2(u64 v, float& lo, float& hi) {
    asm("mov.b64 {%0, %1}, %2;" : "=f"(lo), "=f"(hi) : "l"(v));
}
__device__ __forceinline__ void lds_2u64(unsigned addr, u64& a, u64& b) {
    asm volatile("ld.shared.v2.u64 {%0, %1}, [%2];" : "=l"(a), "=l"(b) : "r"(addr));
}
__device__ __forceinline__ void sts_dup2(unsigned addr, float v) {
    asm volatile("st.shared.v2.f32 [%0], {%1, %2};" :: "r"(addr), "f"(v), "f"(v));
}
__device__ __forceinline__ void sts_dup4(unsigned addr, float a, float b) {
    asm volatile("st.shared.v4.f32 [%0], {%1, %2, %3, %4};"
                 :: "r"(addr), "f"(a), "f"(a), "f"(b), "f"(b));
}

__device__ __forceinline__ float sigmoid_f(float v) {
    return __fdividef(1.0f, 1.0f + __expf(-v));
}
__device__ __forceinline__ float tanh_f(float v) {
    return __fdividef(2.0f, 1.0f + __expf(-2.0f * v)) - 1.0f;
}

__global__ void __launch_bounds__(NTHREADS, 1)
lstm_kernel(const float* __restrict__ x,    // [T, B, 8]
            const float* __restrict__ Wih,  // [8, 80]
            const float* __restrict__ bih,  // [80]
            const float* __restrict__ Whh,  // [20, 80]
            const float* __restrict__ bhh,  // [80]
            const float* __restrict__ hx0,  // [1, 20]
            const float* __restrict__ cx0,  // [1, 20]
            float* __restrict__ out)        // [B, 20]
{
    // duplicated value buffer: row = [(x0,x0)..(x7,x7),(h0,h0)..(h19,h19), pad]
    __shared__ __align__(16) float sv[2][NGE][ROWF];

    const int tid = threadIdx.x;
    const int g   = tid / HID;            // 0..13
    const int j   = tid % HID;            // 0..19
    const int b0  = blockIdx.x * NGE + g;
    const int b1  = b0 + GROUPS;
    const bool ok0 = (b0 < BATCH);
    const bool ok1 = (b1 < BATCH);
    const int cb0 = ok0 ? b0 : 0;
    const int cb1 = ok1 ? b1 : 0;

    const unsigned sbase = (unsigned)__cvta_generic_to_shared(&sv[0][0][0]);
    const unsigned row0  = sbase + (unsigned)g * ROWB;            // elem 0 row (buf 0)
    const unsigned row1  = sbase + (unsigned)(g + GROUPS) * ROWB; // elem 1 row (buf 0)

    // ---- packed weights: w01[k]=(w[k][g0],w[k][g1]), w23[k]=(w[k][g2],w[k][g3]) ----
    u64 w01[KV], w23[KV];
#pragma unroll
    for (int k = 0; k < INSZ; k++) {
        w01[k] = pack2(__ldg(&Wih[k * G4 + 0 * HID + j]), __ldg(&Wih[k * G4 + 1 * HID + j]));
        w23[k] = pack2(__ldg(&Wih[k * G4 + 2 * HID + j]), __ldg(&Wih[k * G4 + 3 * HID + j]));
    }
#pragma unroll
    for (int k = 0; k < HID; k++) {
        w01[INSZ + k] = pack2(__ldg(&Whh[k * G4 + 0 * HID + j]), __ldg(&Whh[k * G4 + 1 * HID + j]));
        w23[INSZ + k] = pack2(__ldg(&Whh[k * G4 + 2 * HID + j]), __ldg(&Whh[k * G4 + 3 * HID + j]));
    }
    const u64 bias01 = pack2(__ldg(&bih[0 * HID + j]) + __ldg(&bhh[0 * HID + j]),
                             __ldg(&bih[1 * HID + j]) + __ldg(&bhh[1 * HID + j]));
    const u64 bias23 = pack2(__ldg(&bih[2 * HID + j]) + __ldg(&bhh[2 * HID + j]),
                             __ldg(&bih[3 * HID + j]) + __ldg(&bhh[3 * HID + j]));

    float h0 = hx0[j], c0 = cx0[j];
    float h1 = h0,     c1 = c0;

    const float4* x4 = reinterpret_cast<const float4*>(x);
    // x float4 index for (t, b, half): (t*BATCH + b)*2 + half

    // ---- prologue: buf0 <- [x_0 ; h_init]; prefetch x_1 ----
    float4 xn0 = make_float4(0.f, 0.f, 0.f, 0.f);
    float4 xn1 = xn0;
    if (j < 2) {
        float4 a0 = x4[(0 * BATCH + cb0) * 2 + j];
        float4 a1 = x4[(0 * BATCH + cb1) * 2 + j];
        sts_dup4(row0 + 32u * j,       a0.x, a0.y);
        sts_dup4(row0 + 32u * j + 16u, a0.z, a0.w);
        sts_dup4(row1 + 32u * j,       a1.x, a1.y);
        sts_dup4(row1 + 32u * j + 16u, a1.z, a1.w);
        xn0 = x4[(1 * BATCH + cb0) * 2 + j];
        xn1 = x4[(1 * BATCH + cb1) * 2 + j];
    }
    sts_dup2(row0 + 64u + 8u * j, h0);
    sts_dup2(row1 + 64u + 8u * j, h1);
    __syncthreads();

    unsigned curoff = 0;
    for (int t = 0; t < T_STEPS; t++) {
        const unsigned nxtoff = curoff ^ BUFB;

        // prefetch x_{t+2}
        float4 xp0 = make_float4(0.f, 0.f, 0.f, 0.f);
        float4 xp1 = xp0;
        if (j < 2 && (t + 2) < T_STEPS) {
            xp0 = x4[((t + 2) * BATCH + cb0) * 2 + j];
            xp1 = x4[((t + 2) * BATCH + cb1) * 2 + j];
        }

        // ---- packed gate accumulation, split even/odd-k partials ----
        u64 e01a = bias01, e23a = bias23, e01b = 0ull, e23b = 0ull;  // elem 0
        u64 f01a = bias01, f23a = bias23, f01b = 0ull, f23b = 0ull;  // elem 1
        const unsigned r0 = row0 + curoff;
        const unsigned r1 = row1 + curoff;
#pragma unroll
        for (int m = 0; m < KV / 2; m++) {
            u64 p0, p1, q0, q1;
            lds_2u64(r0 + 16u * m, p0, p1);   // (v_{2m},v_{2m}), (v_{2m+1},v_{2m+1})
            lds_2u64(r1 + 16u * m, q0, q1);
            e01a = fma2(p0, w01[2 * m], e01a);
            e23a = fma2(p0, w23[2 * m], e23a);
            e01b = fma2(p1, w01[2 * m + 1], e01b);
            e23b = fma2(p1, w23[2 * m + 1], e23b);
            f01a = fma2(q0, w01[2 * m], f01a);
            f23a = fma2(q0, w23[2 * m], f23a);
            f01b = fma2(q1, w01[2 * m + 1], f01b);
            f23b = fma2(q1, w23[2 * m + 1], f23b);
        }
        const u64 e01 = add2(e01a, e01b), e23 = add2(e23a, e23b);
        const u64 f01 = add2(f01a, f01b), f23 = add2(f23a, f23b);

        // ---- activations + state update ----
        {
            float ai, af, ag, ao;
            unpack2(e01, ai, af);
            unpack2(e23, ag, ao);
            float ii = sigmoid_f(ai);
            float ff = sigmoid_f(af);
            float gg = tanh_f(ag);
            float oo = sigmoid_f(ao);
            c0 = ff * c0 + ii * gg;
            h0 = oo * tanh_f(c0);
        }
        {
            float ai, af, ag, ao;
            unpack2(f01, ai, af);
            unpack2(f23, ag, ao);
            float ii = sigmoid_f(ai);
            float ff = sigmoid_f(af);
            float gg = tanh_f(ag);
            float oo = sigmoid_f(ao);
            c1 = ff * c1 + ii * gg;
            h1 = oo * tanh_f(c1);
        }

        if (t + 1 < T_STEPS) {
            sts_dup2(row0 + nxtoff + 64u + 8u * j, h0);
            sts_dup2(row1 + nxtoff + 64u + 8u * j, h1);
            if (j < 2) {
                sts_dup4(row0 + nxtoff + 32u * j,       xn0.x, xn0.y);
                sts_dup4(row0 + nxtoff + 32u * j + 16u, xn0.z, xn0.w);
                sts_dup4(row1 + nxtoff + 32u * j,       xn1.x, xn1.y);
                sts_dup4(row1 + nxtoff + 32u * j + 16u, xn1.z, xn1.w);
                xn0 = xp0;
                xn1 = xp1;
            }
            __syncthreads();
        }
        curoff = nxtoff;
    }

    if (ok0) out[b0 * HID + j] = h0;
    if (ok1) out[b1 * HID + j] = h1;
}

extern "C" void kernel_launch(void* const* d_in, const int* in_sizes, int n_in,
                              void* d_out, int out_size) {
    const float* x   = (const float*)d_in[0];
    const float* Wih = (const float*)d_in[1];
    const float* bih = (const float*)d_in[2];
    const float* Whh = (const float*)d_in[3];
    const float* bhh = (const float*)d_in[4];
    const float* hx0 = (const float*)d_in[5];
    const float* cx0 = (const float*)d_in[6];
    float* out = (float*)d_out;

    const int grid = (BATCH + NGE - 1) / NGE;  // 147
    lstm_kernel<<<grid, NTHREADS>>>(x, Wih, bih, Whh, bhh, hx0, cx0, out);
}